// round 2
// baseline (speedup 1.0000x reference)
#include <cuda_runtime.h>
#include <math.h>

#define BB 4
#define NN 4096
#define CC 64
#define ALPHA 0.2f

// ---------------- scratch (static device globals; no allocation) ----------------
__device__ float g_h[BB*NN*CC];       // h = feat @ W
__device__ float g_s1[BB*NN];
__device__ float g_s2[BB*NN];
__device__ float g_M2[BB];
__device__ float g_sval[BB*NN];       // sorted s2 (ascending) per batch
__device__ int   g_sidx[BB*NN];       // permutation
__device__ float g_E1[BB*NN];         // exp(sval - M2)
__device__ float g_E2[BB*NN];         // exp(alpha * sval)
__device__ float g_SgeH[BB*(NN+1)*CC]; // suffix sums of E1*h (sorted order)
__device__ float g_SltH[BB*(NN+1)*CC]; // prefix sums of E2*h (sorted order)
__device__ float g_Sge1[BB*(NN+1)];
__device__ float g_Slt1[BB*(NN+1)];

// ---------------- K1: h = feat @ W, s1 = h.a1, s2 = h.a2 ----------------
// 4 rows per block; 64 threads per row (one per output channel).
__global__ void k1_hsw(const float* __restrict__ feat,
                       const float* __restrict__ W,
                       const float* __restrict__ a)
{
    __shared__ float Ws[64*64];
    __shared__ float a1s[64], a2s[64];
    __shared__ float fs[4][64];
    __shared__ float p1[4][64], p2[4][64];

    int tid = threadIdx.x;                 // 256
    for (int i = tid; i < 64*64; i += 256) Ws[i] = W[i];
    if (tid < 64) { a1s[tid] = a[tid]; a2s[tid] = a[64 + tid]; }

    int rb  = tid >> 6;                    // 0..3
    int c   = tid & 63;
    int row = blockIdx.x * 4 + rb;         // 0 .. B*N-1

    fs[rb][c] = feat[row*64 + c];
    __syncthreads();

    float acc = 0.f;
    #pragma unroll
    for (int k = 0; k < 64; k++)
        acc = fmaf(fs[rb][k], Ws[k*64 + c], acc);

    g_h[row*64 + c] = acc;
    p1[rb][c] = acc * a1s[c];
    p2[rb][c] = acc * a2s[c];
    __syncthreads();

    for (int s = 32; s > 0; s >>= 1) {
        if (c < s) { p1[rb][c] += p1[rb][c+s]; p2[rb][c] += p2[rb][c+s]; }
        __syncthreads();
    }
    if (c == 0) { g_s1[row] = p1[rb][0]; g_s2[row] = p2[rb][0]; }
}

// ---------------- K1b: per-batch max of s2 ----------------
__global__ void k1b_max()
{
    int b = blockIdx.x;
    __shared__ float red[256];
    int tid = threadIdx.x;
    float m = -INFINITY;
    for (int i = tid; i < NN; i += 256) m = fmaxf(m, g_s2[b*NN + i]);
    red[tid] = m; __syncthreads();
    for (int s = 128; s > 0; s >>= 1) {
        if (tid < s) red[tid] = fmaxf(red[tid], red[tid+s]);
        __syncthreads();
    }
    if (tid == 0) g_M2[b] = red[0];
}

// ---------------- K2: bitonic sort of s2 per batch (ascending) + exp tables ----------------
__global__ __launch_bounds__(1024) void k2_sort()
{
    int b = blockIdx.x;
    __shared__ float sv[NN];
    __shared__ int   si[NN];
    int tid = threadIdx.x;                 // 1024

    for (int i = tid; i < NN; i += 1024) { sv[i] = g_s2[b*NN + i]; si[i] = i; }
    __syncthreads();

    for (int k = 2; k <= NN; k <<= 1) {
        for (int j = k >> 1; j > 0; j >>= 1) {
            for (int i = tid; i < NN; i += 1024) {
                int ixj = i ^ j;
                if (ixj > i) {
                    float va = sv[i], vb = sv[ixj];
                    bool asc = ((i & k) == 0);
                    bool sw  = asc ? (va > vb) : (va < vb);
                    if (sw) {
                        sv[i] = vb; sv[ixj] = va;
                        int t = si[i]; si[i] = si[ixj]; si[ixj] = t;
                    }
                }
            }
            __syncthreads();
        }
    }

    float M2 = g_M2[b];
    for (int i = tid; i < NN; i += 1024) {
        float v = sv[i];
        g_sval[b*NN + i] = v;
        g_sidx[b*NN + i] = si[i];
        g_E1[b*NN + i] = expf(v - M2);
        g_E2[b*NN + i] = expf(ALPHA * v);
    }
}

// ---------------- K3: prefix(Slt, E2) and suffix(Sge, E1) scans of E*h over sorted order ----
// One block per batch: 16 chunks x 64 channels.
__global__ __launch_bounds__(1024) void k3_scan()
{
    int b     = blockIdx.x;
    int tid   = threadIdx.x;
    int chunk = tid >> 6;      // 0..15
    int c     = tid & 63;
    const int CH = NN / 16;    // 256
    int base  = chunk * CH;

    const float* hB   = g_h   + (size_t)b*NN*CC;
    const int*   sidx = g_sidx + b*NN;
    const float* E1   = g_E1  + b*NN;
    const float* E2   = g_E2  + b*NN;
    float* SltH = g_SltH + (size_t)b*(NN+1)*CC;
    float* SgeH = g_SgeH + (size_t)b*(NN+1)*CC;
    float* Slt1 = g_Slt1 + b*(NN+1);
    float* Sge1 = g_Sge1 + b*(NN+1);

    __shared__ float pl[16][64], pg[16][64];
    __shared__ float pls[16], pgs[16];

    // Phase A: chunk partial sums
    float accL = 0.f, accG = 0.f, sL = 0.f, sG = 0.f;
    for (int k = base; k < base + CH; k++) {
        int   j  = sidx[k];
        float hv = hB[j*64 + c];
        float e1 = E1[k], e2 = E2[k];
        accL = fmaf(e2, hv, accL);
        accG = fmaf(e1, hv, accG);
        if (c == 0) { sL += e2; sG += e1; }
    }
    pl[chunk][c] = accL; pg[chunk][c] = accG;
    if (c == 0) { pls[chunk] = sL; pgs[chunk] = sG; }
    __syncthreads();

    // Phase B: offsets
    float offL = 0.f, offG = 0.f, offLs = 0.f, offGs = 0.f;
    for (int t = 0; t < chunk; t++)     { offL += pl[t][c]; offLs += pls[t]; }
    for (int t = chunk + 1; t < 16; t++){ offG += pg[t][c]; offGs += pgs[t]; }

    // Phase C1: prefix (lt branch, E2), exclusive: Slt[k] = sum over t<k
    float acc = offL, accs = offLs;
    for (int k = base; k < base + CH; k++) {
        SltH[(size_t)k*64 + c] = acc;
        if (c == 0) Slt1[k] = accs;
        int   j  = sidx[k];
        float hv = hB[j*64 + c];
        float e2 = E2[k];
        acc = fmaf(e2, hv, acc);
        if (c == 0) accs += e2;
    }
    if (chunk == 15) { SltH[(size_t)NN*64 + c] = acc; if (c == 0) Slt1[NN] = accs; }

    // Phase C2: suffix (ge branch, E1), inclusive from k: Sge[k] = sum over t>=k
    acc = offG; accs = offGs;
    if (chunk == 15) { SgeH[(size_t)NN*64 + c] = 0.f; if (c == 0) Sge1[NN] = 0.f; }
    for (int k = base + CH - 1; k >= base; k--) {
        int   j  = sidx[k];
        float hv = hB[j*64 + c];
        float e1 = E1[k];
        acc = fmaf(e1, hv, acc);
        SgeH[(size_t)k*64 + c] = acc;
        if (c == 0) { accs += e1; Sge1[k] = accs; }
    }
}

// ---------------- K4: per-row threshold lookup + combine ----------------
// One warp per output row; lane handles 2 channels.
__global__ void k4_out(float* __restrict__ out)
{
    int gw   = (blockIdx.x * blockDim.x + threadIdx.x) >> 5;
    int lane = threadIdx.x & 31;
    if (gw >= BB*NN) return;
    int b = gw >> 12;

    float s1v = g_s1[gw];
    float M2  = g_M2[b];
    float thr = -s1v;

    // lower_bound: first index with sval >= thr (uniform across warp)
    const float* sval = g_sval + b*NN;
    int lo = 0, hi = NN;
    while (lo < hi) {
        int mid = (lo + hi) >> 1;
        if (sval[mid] < thr) lo = mid + 1; else hi = mid;
    }
    int k = lo;

    float x = s1v + M2;
    float m = (x >= 0.f) ? x : ALPHA * x;       // row max of lrelu logits
    float cge = expf(x - m);                    // pairs with E1 = exp(s2 - M2)
    float clt = expf(ALPHA * s1v - m);          // pairs with E2 = exp(alpha*s2)

    const float* SgeH = g_SgeH + ((size_t)b*(NN+1) + k)*64;
    const float* SltH = g_SltH + ((size_t)b*(NN+1) + k)*64;
    float denom = cge * g_Sge1[b*(NN+1) + k] + clt * g_Slt1[b*(NN+1) + k];
    float inv = 1.f / denom;

    float ge0 = SgeH[2*lane],   ge1 = SgeH[2*lane+1];
    float lt0 = SltH[2*lane],   lt1 = SltH[2*lane+1];
    float o0 = (cge*ge0 + clt*lt0) * inv;
    float o1 = (cge*ge1 + clt*lt1) * inv;

    float2* op = (float2*)(out + (size_t)gw*64);
    op[lane] = make_float2(o0, o1);
}

// ---------------- launch ----------------
extern "C" void kernel_launch(void* const* d_in, const int* in_sizes, int n_in,
                              void* d_out, int out_size)
{
    const float* feat = (const float*)d_in[0];
    // d_in[1] = adj: unused by the reference computation — deliberately not read.
    const float* W    = (const float*)d_in[2];
    const float* a    = (const float*)d_in[3];
    float* out = (float*)d_out;

    k1_hsw<<<(BB*NN)/4, 256>>>(feat, W, a);
    k1b_max<<<BB, 256>>>();
    k2_sort<<<BB, 1024>>>();
    k3_scan<<<BB, 1024>>>();
    k4_out<<<(BB*NN*32)/256, 256>>>(out);
}

// round 3
// speedup vs baseline: 1.5389x; 1.5389x over previous
#include <cuda_runtime.h>
#include <math.h>

#define BB 4
#define NN 4096
#define CC 64
#define ALPHA 0.2f
#define G  128          // scan chunks per batch
#define CH 32           // elements per chunk (NN = G*CH)
#define FULL 0xffffffffu

// ---------------- scratch (static device globals; no allocation) ----------------
__device__ float g_h[BB*NN*CC];        // h = feat @ W
__device__ float g_s1[BB*NN];
__device__ float g_s2[BB*NN];
__device__ float g_M2[BB];
__device__ float g_sval[BB*NN];        // sorted s2 (ascending) per batch
__device__ int   g_sidx[BB*NN];        // permutation
__device__ float g_E1[BB*NN];          // exp(sval - M2)
__device__ float g_E2[BB*NN];          // exp(alpha * sval)
__device__ float g_SgeH[BB*(NN+1)*CC]; // suffix sums of E1*h (sorted order)
__device__ float g_SltH[BB*(NN+1)*CC]; // prefix sums of E2*h (sorted order)
__device__ float g_Sge1[BB*(NN+1)];
__device__ float g_Slt1[BB*(NN+1)];
// scan intermediates
__device__ float g_pl [BB*G*CC], g_pg [BB*G*CC];  // chunk partials (vector)
__device__ float g_pls[BB*G],    g_pgs[BB*G];     // chunk partials (scalar)
__device__ float g_ofL[BB*G*CC], g_ofG[BB*G*CC];  // chunk offsets (vector)
__device__ float g_ofLs[BB*G],   g_ofGs[BB*G];    // chunk offsets (scalar)

// ---------------- K1: h = feat @ W, s1 = h.a1, s2 = h.a2 ----------------
// 16 rows per block (4 at a time); W staged once per block.
__global__ __launch_bounds__(256) void k1_hsw(const float* __restrict__ feat,
                                              const float* __restrict__ W,
                                              const float* __restrict__ a)
{
    __shared__ float Ws[64*64];
    __shared__ float a1s[64], a2s[64];
    __shared__ float fs[4][64];
    __shared__ float p1[4][2], p2[4][2];

    int tid = threadIdx.x;                 // 256
    for (int i = tid; i < 64*64; i += 256) Ws[i] = W[i];
    if (tid < 64) { a1s[tid] = a[tid]; a2s[tid] = a[64 + tid]; }

    int rb = tid >> 6;                     // 0..3
    int c  = tid & 63;

    #pragma unroll
    for (int r = 0; r < 4; r++) {
        int row = blockIdx.x * 16 + r * 4 + rb;
        fs[rb][c] = feat[row*64 + c];
        __syncthreads();

        float acc = 0.f;
        #pragma unroll
        for (int k = 0; k < 64; k++)
            acc = fmaf(fs[rb][k], Ws[k*64 + c], acc);
        g_h[row*64 + c] = acc;

        float v1 = acc * a1s[c];
        float v2 = acc * a2s[c];
        #pragma unroll
        for (int o = 16; o > 0; o >>= 1) {
            v1 += __shfl_down_sync(FULL, v1, o);
            v2 += __shfl_down_sync(FULL, v2, o);
        }
        if ((c & 31) == 0) { p1[rb][c>>5] = v1; p2[rb][c>>5] = v2; }
        __syncthreads();
        if (c == 0) {
            g_s1[row] = p1[rb][0] + p1[rb][1];
            g_s2[row] = p2[rb][0] + p2[rb][1];
        }
    }
}

// ---------------- K1b: per-batch max of s2 ----------------
__global__ void k1b_max()
{
    int b = blockIdx.x;
    __shared__ float red[256];
    int tid = threadIdx.x;
    float m = -INFINITY;
    for (int i = tid; i < NN; i += 256) m = fmaxf(m, g_s2[b*NN + i]);
    red[tid] = m; __syncthreads();
    for (int s = 128; s > 0; s >>= 1) {
        if (tid < s) red[tid] = fmaxf(red[tid], red[tid+s]);
        __syncthreads();
    }
    if (tid == 0) g_M2[b] = red[0];
}

// ---------------- K2: bitonic sort of s2 per batch (ascending) + exp tables ----------------
__global__ __launch_bounds__(1024) void k2_sort()
{
    int b = blockIdx.x;
    __shared__ float sv[NN];
    __shared__ int   si[NN];
    int tid = threadIdx.x;                 // 1024

    for (int i = tid; i < NN; i += 1024) { sv[i] = g_s2[b*NN + i]; si[i] = i; }
    __syncthreads();

    for (int k = 2; k <= NN; k <<= 1) {
        for (int j = k >> 1; j > 0; j >>= 1) {
            for (int i = tid; i < NN; i += 1024) {
                int ixj = i ^ j;
                if (ixj > i) {
                    float va = sv[i], vb = sv[ixj];
                    bool asc = ((i & k) == 0);
                    bool sw  = asc ? (va > vb) : (va < vb);
                    if (sw) {
                        sv[i] = vb; sv[ixj] = va;
                        int t = si[i]; si[i] = si[ixj]; si[ixj] = t;
                    }
                }
            }
            __syncthreads();
        }
    }

    float M2 = g_M2[b];
    for (int i = tid; i < NN; i += 1024) {
        float v = sv[i];
        g_sval[b*NN + i] = v;
        g_sidx[b*NN + i] = si[i];
        g_E1[b*NN + i] = expf(v - M2);
        g_E2[b*NN + i] = expf(ALPHA * v);
    }
}

// ---------------- K3a: chunk partial sums (grid = BB*G, block = 64) ----------------
__global__ __launch_bounds__(64) void k3a_partial()
{
    int bg = blockIdx.x;            // b*G + g
    int b  = bg >> 7;               // /G
    int g  = bg & (G-1);
    int c  = threadIdx.x;           // 0..63
    int base = g * CH;

    const float* hB   = g_h    + (size_t)b*NN*CC;
    const int*   sidx = g_sidx + b*NN;
    const float* E1   = g_E1   + b*NN;
    const float* E2   = g_E2   + b*NN;

    float accL = 0.f, accG = 0.f;
    #pragma unroll
    for (int k = base; k < base + CH; k++) {
        float hv = hB[(size_t)sidx[k]*64 + c];
        accL = fmaf(E2[k], hv, accL);
        accG = fmaf(E1[k], hv, accG);
    }
    g_pl[(size_t)bg*64 + c] = accL;
    g_pg[(size_t)bg*64 + c] = accG;

    // scalar chunk sums: warp0 sums E2, warp1 sums E1 (CH == 32 lanes)
    int w = c >> 5, l = c & 31;
    float e = (w == 0) ? E2[base + l] : E1[base + l];
    #pragma unroll
    for (int o = 16; o > 0; o >>= 1) e += __shfl_down_sync(FULL, e, o);
    if (l == 0) {
        if (w == 0) g_pls[bg] = e; else g_pgs[bg] = e;
    }
}

// ---------------- K3b: scan over chunk partials (grid = BB, block = 64) ----------------
__global__ __launch_bounds__(64) void k3b_offsets()
{
    int b = blockIdx.x;
    int c = threadIdx.x;

    float acc = 0.f;
    for (int g = 0; g < G; g++) {          // exclusive prefix
        size_t idx = (size_t)(b*G + g)*64 + c;
        g_ofL[idx] = acc;
        acc += g_pl[idx];
    }
    acc = 0.f;
    for (int g = G-1; g >= 0; g--) {       // exclusive suffix
        size_t idx = (size_t)(b*G + g)*64 + c;
        g_ofG[idx] = acc;
        acc += g_pg[idx];
    }
    if (c == 0) {
        float s = 0.f;
        for (int g = 0; g < G; g++)   { g_ofLs[b*G + g] = s; s += g_pls[b*G + g]; }
        s = 0.f;
        for (int g = G-1; g >= 0; g--){ g_ofGs[b*G + g] = s; s += g_pgs[b*G + g]; }
    }
}

// ---------------- K3c: write scan tables (grid = BB*G, block = 64) ----------------
__global__ __launch_bounds__(64) void k3c_tables()
{
    int bg = blockIdx.x;
    int b  = bg >> 7;
    int g  = bg & (G-1);
    int c  = threadIdx.x;
    int base = g * CH;

    const float* hB   = g_h    + (size_t)b*NN*CC;
    const int*   sidx = g_sidx + b*NN;
    const float* E1   = g_E1   + b*NN;
    const float* E2   = g_E2   + b*NN;
    float* SltH = g_SltH + (size_t)b*(NN+1)*CC;
    float* SgeH = g_SgeH + (size_t)b*(NN+1)*CC;
    float* Slt1 = g_Slt1 + b*(NN+1);
    float* Sge1 = g_Sge1 + b*(NN+1);

    // prefix (lt branch, E2), exclusive
    float acc  = g_ofL[(size_t)bg*64 + c];
    float accs = g_ofLs[bg];
    #pragma unroll
    for (int k = base; k < base + CH; k++) {
        SltH[(size_t)k*64 + c] = acc;
        if (c == 0) Slt1[k] = accs;
        float hv = hB[(size_t)sidx[k]*64 + c];
        float e2 = E2[k];
        acc = fmaf(e2, hv, acc);
        if (c == 0) accs += e2;
    }
    if (g == G-1) { SltH[(size_t)NN*64 + c] = acc; if (c == 0) Slt1[NN] = accs; }

    // suffix (ge branch, E1), inclusive from k
    acc  = g_ofG[(size_t)bg*64 + c];
    accs = g_ofGs[bg];
    if (g == G-1) { SgeH[(size_t)NN*64 + c] = 0.f; if (c == 0) Sge1[NN] = 0.f; }
    #pragma unroll
    for (int k = base + CH - 1; k >= base; k--) {
        float hv = hB[(size_t)sidx[k]*64 + c];
        float e1 = E1[k];
        acc = fmaf(e1, hv, acc);
        SgeH[(size_t)k*64 + c] = acc;
        if (c == 0) { accs += e1; Sge1[k] = accs; }
    }
}

// ---------------- K4: per-row threshold lookup + combine ----------------
// One warp per output row; lane handles 2 channels.
__global__ void k4_out(float* __restrict__ out)
{
    int gw   = (blockIdx.x * blockDim.x + threadIdx.x) >> 5;
    int lane = threadIdx.x & 31;
    if (gw >= BB*NN) return;
    int b = gw >> 12;

    float s1v = g_s1[gw];
    float M2  = g_M2[b];
    float thr = -s1v;

    // lower_bound: first index with sval >= thr (uniform across warp)
    const float* sval = g_sval + b*NN;
    int lo = 0, hi = NN;
    while (lo < hi) {
        int mid = (lo + hi) >> 1;
        if (sval[mid] < thr) lo = mid + 1; else hi = mid;
    }
    int k = lo;

    float x = s1v + M2;
    float m = (x >= 0.f) ? x : ALPHA * x;       // row max of lrelu logits
    float cge = expf(x - m);                    // pairs with E1 = exp(s2 - M2)
    float clt = expf(ALPHA * s1v - m);          // pairs with E2 = exp(alpha*s2)

    const float* SgeH = g_SgeH + ((size_t)b*(NN+1) + k)*64;
    const float* SltH = g_SltH + ((size_t)b*(NN+1) + k)*64;
    float denom = cge * g_Sge1[b*(NN+1) + k] + clt * g_Slt1[b*(NN+1) + k];
    float inv = 1.f / denom;

    float ge0 = SgeH[2*lane],   ge1 = SgeH[2*lane+1];
    float lt0 = SltH[2*lane],   lt1 = SltH[2*lane+1];
    float o0 = (cge*ge0 + clt*lt0) * inv;
    float o1 = (cge*ge1 + clt*lt1) * inv;

    float2* op = (float2*)(out + (size_t)gw*64);
    op[lane] = make_float2(o0, o1);
}

// ---------------- launch ----------------
extern "C" void kernel_launch(void* const* d_in, const int* in_sizes, int n_in,
                              void* d_out, int out_size)
{
    const float* feat = (const float*)d_in[0];
    // d_in[1] = adj: unused by the reference computation — deliberately not read.
    const float* W    = (const float*)d_in[2];
    const float* a    = (const float*)d_in[3];
    float* out = (float*)d_out;

    k1_hsw<<<(BB*NN)/16, 256>>>(feat, W, a);
    k1b_max<<<BB, 256>>>();
    k2_sort<<<BB, 1024>>>();
    k3a_partial<<<BB*G, 64>>>();
    k3b_offsets<<<BB, 64>>>();
    k3c_tables<<<BB*G, 64>>>();
    k4_out<<<(BB*NN*32)/256, 256>>>(out);
}

// round 4
// speedup vs baseline: 2.7670x; 1.7981x over previous
#include <cuda_runtime.h>
#include <math.h>

#define BB 4
#define NN 4096
#define CC 64
#define ALPHA 0.2f
#define G  128          // scan chunks per batch
#define CH 32           // elements per chunk (NN = G*CH)
#define FULL 0xffffffffu

// ---------------- scratch (static device globals; no allocation) ----------------
__device__ float g_h[BB*NN*CC];        // h = feat @ W
__device__ float g_s1[BB*NN];
__device__ float g_s2[BB*NN];
__device__ float g_M2[BB];
__device__ float g_sval[BB*NN];        // sorted s2 (ascending) per batch
__device__ int   g_sidx[BB*NN];        // permutation
__device__ float g_E1[BB*NN];          // exp(sval - M2)
__device__ float g_E2[BB*NN];          // exp(alpha * sval)
__device__ float g_SgeH[BB*(NN+1)*CC]; // suffix sums of E1*h (sorted order)
__device__ float g_SltH[BB*(NN+1)*CC]; // prefix sums of E2*h (sorted order)
__device__ float g_Sge1[BB*(NN+1)];
__device__ float g_Slt1[BB*(NN+1)];
// scan intermediates
__device__ float g_pl [BB*G*CC], g_pg [BB*G*CC];  // chunk partials (vector)
__device__ float g_pls[BB*G],    g_pgs[BB*G];     // chunk partials (scalar)
__device__ float g_ofL[BB*G*CC], g_ofG[BB*G*CC];  // chunk offsets (vector)
__device__ float g_ofLs[BB*G],   g_ofGs[BB*G];    // chunk offsets (scalar)

// ---------------- K1: h = feat @ W, s1 = h.a1, s2 = h.a2 ----------------
__global__ __launch_bounds__(256) void k1_hsw(const float* __restrict__ feat,
                                              const float* __restrict__ W,
                                              const float* __restrict__ a)
{
    __shared__ float Ws[64*64];
    __shared__ float a1s[64], a2s[64];
    __shared__ float fs[4][64];
    __shared__ float p1[4][2], p2[4][2];

    int tid = threadIdx.x;                 // 256
    for (int i = tid; i < 64*64; i += 256) Ws[i] = W[i];
    if (tid < 64) { a1s[tid] = a[tid]; a2s[tid] = a[64 + tid]; }

    int rb = tid >> 6;                     // 0..3
    int c  = tid & 63;

    #pragma unroll
    for (int r = 0; r < 4; r++) {
        int row = blockIdx.x * 16 + r * 4 + rb;
        fs[rb][c] = feat[row*64 + c];
        __syncthreads();

        float acc = 0.f;
        #pragma unroll
        for (int k = 0; k < 64; k++)
            acc = fmaf(fs[rb][k], Ws[k*64 + c], acc);
        g_h[row*64 + c] = acc;

        float v1 = acc * a1s[c];
        float v2 = acc * a2s[c];
        #pragma unroll
        for (int o = 16; o > 0; o >>= 1) {
            v1 += __shfl_down_sync(FULL, v1, o);
            v2 += __shfl_down_sync(FULL, v2, o);
        }
        if ((c & 31) == 0) { p1[rb][c>>5] = v1; p2[rb][c>>5] = v2; }
        __syncthreads();
        if (c == 0) {
            g_s1[row] = p1[rb][0] + p1[rb][1];
            g_s2[row] = p2[rb][0] + p2[rb][1];
        }
    }
}

// ---------------- K2: bitonic sort of s2 per batch (ascending) + M2 + exp tables ------
// Pass with exchange distance j<32 stays inside a warp's 32-element window, so
// only __syncwarp is needed there; full barrier only when j>=16 (previous pass j>=32).
__global__ __launch_bounds__(1024) void k2_sort()
{
    int b = blockIdx.x;
    __shared__ float sv[NN];
    __shared__ int   si[NN];
    int tid = threadIdx.x;                 // 1024

    for (int i = tid; i < NN; i += 1024) { sv[i] = g_s2[b*NN + i]; si[i] = i; }
    __syncthreads();

    for (int k = 2; k <= NN; k <<= 1) {
        for (int j = k >> 1; j > 0; j >>= 1) {
            #pragma unroll 4
            for (int i = tid; i < NN; i += 1024) {
                int ixj = i ^ j;
                if (ixj > i) {
                    float va = sv[i], vb = sv[ixj];
                    bool asc = ((i & k) == 0);
                    bool sw  = asc ? (va > vb) : (va < vb);
                    if (sw) {
                        sv[i] = vb; sv[ixj] = va;
                        int t = si[i]; si[i] = si[ixj]; si[ixj] = t;
                    }
                }
            }
            if (j >= 8) __syncthreads(); else __syncwarp();
        }
        __syncthreads();
    }

    float M2 = sv[NN-1];                   // max of s2 (sorted ascending)
    if (tid == 0) g_M2[b] = M2;
    for (int i = tid; i < NN; i += 1024) {
        float v = sv[i];
        g_sval[b*NN + i] = v;
        g_sidx[b*NN + i] = si[i];
        g_E1[b*NN + i] = expf(v - M2);
        g_E2[b*NN + i] = expf(ALPHA * v);
    }
}

// ---------------- K3a: chunk partial sums (grid = BB*G/4, block = 256) ----------------
__global__ __launch_bounds__(256) void k3a_partial()
{
    int tid = threadIdx.x;
    int rb  = tid >> 6;                   // chunk within block
    int c   = tid & 63;
    int bg  = blockIdx.x * 4 + rb;        // b*G + g
    int b   = bg >> 7;
    int g   = bg & (G-1);
    int base = g * CH;

    const float* hB   = g_h    + (size_t)b*NN*CC;
    const int*   sidx = g_sidx + b*NN;
    const float* E1   = g_E1   + b*NN;
    const float* E2   = g_E2   + b*NN;

    float accL = 0.f, accG = 0.f;
    #pragma unroll
    for (int k = base; k < base + CH; k++) {
        float hv = hB[(size_t)sidx[k]*64 + c];
        accL = fmaf(E2[k], hv, accL);
        accG = fmaf(E1[k], hv, accG);
    }
    g_pl[(size_t)bg*64 + c] = accL;
    g_pg[(size_t)bg*64 + c] = accG;

    // scalar chunk sums: within each 64-thread group, warp0 sums E2, warp1 sums E1
    int w = (tid >> 5) & 1, l = tid & 31;
    float e = (w == 0) ? E2[base + l] : E1[base + l];
    #pragma unroll
    for (int o = 16; o > 0; o >>= 1) e += __shfl_down_sync(FULL, e, o);
    if (l == 0) {
        if (w == 0) g_pls[bg] = e; else g_pgs[bg] = e;
    }
}

// ---------------- K3b: parallel scan over the 128 chunk partials ----------------
// grid = BB*(CC+1); block = 128 (one thread per chunk). c==CC handles the scalars.
__global__ __launch_bounds__(128) void k3b_offsets()
{
    int bx = blockIdx.x;
    int b  = bx / (CC + 1);
    int c  = bx % (CC + 1);
    int g  = threadIdx.x;                 // 0..127

    __shared__ float s[G];

    float pl, pg;
    if (c < CC) {
        pl = g_pl[(size_t)(b*G + g)*64 + c];
        pg = g_pg[(size_t)(b*G + g)*64 + c];
    } else {
        pl = g_pls[b*G + g];
        pg = g_pgs[b*G + g];
    }

    // inclusive prefix scan of pl
    s[g] = pl; __syncthreads();
    #pragma unroll
    for (int off = 1; off < G; off <<= 1) {
        float v = (g >= off) ? s[g - off] : 0.f;
        __syncthreads();
        s[g] += v;
        __syncthreads();
    }
    float ofL = (g > 0) ? s[g - 1] : 0.f;   // exclusive prefix
    __syncthreads();

    // inclusive suffix scan of pg
    s[g] = pg; __syncthreads();
    #pragma unroll
    for (int off = 1; off < G; off <<= 1) {
        float v = (g + off < G) ? s[g + off] : 0.f;
        __syncthreads();
        s[g] += v;
        __syncthreads();
    }
    float ofG = (g < G - 1) ? s[g + 1] : 0.f;  // exclusive suffix

    if (c < CC) {
        g_ofL[(size_t)(b*G + g)*64 + c] = ofL;
        g_ofG[(size_t)(b*G + g)*64 + c] = ofG;
    } else {
        g_ofLs[b*G + g] = ofL;
        g_ofGs[b*G + g] = ofG;
    }
}

// ---------------- K3c: write scan tables (grid = BB*G/4, block = 256) ----------------
__global__ __launch_bounds__(256) void k3c_tables()
{
    int tid = threadIdx.x;
    int rb  = tid >> 6;
    int c   = tid & 63;
    int bg  = blockIdx.x * 4 + rb;
    int b   = bg >> 7;
    int g   = bg & (G-1);
    int base = g * CH;

    const float* hB   = g_h    + (size_t)b*NN*CC;
    const int*   sidx = g_sidx + b*NN;
    const float* E1   = g_E1   + b*NN;
    const float* E2   = g_E2   + b*NN;
    float* SltH = g_SltH + (size_t)b*(NN+1)*CC;
    float* SgeH = g_SgeH + (size_t)b*(NN+1)*CC;
    float* Slt1 = g_Slt1 + b*(NN+1);
    float* Sge1 = g_Sge1 + b*(NN+1);

    // prefix (lt branch, E2), exclusive
    float acc  = g_ofL[(size_t)bg*64 + c];
    float accs = g_ofLs[bg];
    #pragma unroll
    for (int k = base; k < base + CH; k++) {
        SltH[(size_t)k*64 + c] = acc;
        if (c == 0) Slt1[k] = accs;
        float hv = hB[(size_t)sidx[k]*64 + c];
        float e2 = E2[k];
        acc = fmaf(e2, hv, acc);
        if (c == 0) accs += e2;
    }
    if (g == G-1) { SltH[(size_t)NN*64 + c] = acc; if (c == 0) Slt1[NN] = accs; }

    // suffix (ge branch, E1), inclusive from k
    acc  = g_ofG[(size_t)bg*64 + c];
    accs = g_ofGs[bg];
    if (g == G-1) { SgeH[(size_t)NN*64 + c] = 0.f; if (c == 0) Sge1[NN] = 0.f; }
    #pragma unroll
    for (int k = base + CH - 1; k >= base; k--) {
        float hv = hB[(size_t)sidx[k]*64 + c];
        float e1 = E1[k];
        acc = fmaf(e1, hv, acc);
        SgeH[(size_t)k*64 + c] = acc;
        if (c == 0) { accs += e1; Sge1[k] = accs; }
    }
}

// ---------------- K4: per-row threshold lookup + combine ----------------
__global__ void k4_out(float* __restrict__ out)
{
    int gw   = (blockIdx.x * blockDim.x + threadIdx.x) >> 5;
    int lane = threadIdx.x & 31;
    if (gw >= BB*NN) return;
    int b = gw >> 12;

    float s1v = g_s1[gw];
    float M2  = g_M2[b];
    float thr = -s1v;

    // lower_bound: first index with sval >= thr (uniform across warp)
    const float* sval = g_sval + b*NN;
    int lo = 0, hi = NN;
    while (lo < hi) {
        int mid = (lo + hi) >> 1;
        if (sval[mid] < thr) lo = mid + 1; else hi = mid;
    }
    int k = lo;

    float x = s1v + M2;
    float m = (x >= 0.f) ? x : ALPHA * x;       // row max of lrelu logits
    float cge = expf(x - m);                    // pairs with E1 = exp(s2 - M2)
    float clt = expf(ALPHA * s1v - m);          // pairs with E2 = exp(alpha*s2)

    const float* SgeH = g_SgeH + ((size_t)b*(NN+1) + k)*64;
    const float* SltH = g_SltH + ((size_t)b*(NN+1) + k)*64;
    float denom = cge * g_Sge1[b*(NN+1) + k] + clt * g_Slt1[b*(NN+1) + k];
    float inv = 1.f / denom;

    float ge0 = SgeH[2*lane],   ge1 = SgeH[2*lane+1];
    float lt0 = SltH[2*lane],   lt1 = SltH[2*lane+1];
    float o0 = (cge*ge0 + clt*lt0) * inv;
    float o1 = (cge*ge1 + clt*lt1) * inv;

    float2* op = (float2*)(out + (size_t)gw*64);
    op[lane] = make_float2(o0, o1);
}

// ---------------- launch ----------------
extern "C" void kernel_launch(void* const* d_in, const int* in_sizes, int n_in,
                              void* d_out, int out_size)
{
    const float* feat = (const float*)d_in[0];
    // d_in[1] = adj: unused by the reference computation — deliberately not read.
    const float* W    = (const float*)d_in[2];
    const float* a    = (const float*)d_in[3];
    float* out = (float*)d_out;

    k1_hsw<<<(BB*NN)/16, 256>>>(feat, W, a);
    k2_sort<<<BB, 1024>>>();
    k3a_partial<<<BB*G/4, 256>>>();
    k3b_offsets<<<BB*(CC+1), 128>>>();
    k3c_tables<<<BB*G/4, 256>>>();
    k4_out<<<(BB*NN*32)/256, 256>>>(out);
}